// round 7
// baseline (speedup 1.0000x reference)
#include <cuda_runtime.h>
#include <cstdint>

#define N_NODES 100000
#define N_EDGES 3200000
#define F_IN    128
#define F_HID   16
#define F_OUT   20

#define SCAN_B  512
#define SCAN_NB ((N_NODES + SCAN_B - 1) / SCAN_B)   // 196

// ---------------- scratch (static device globals; no allocation) ----------------
__device__ int g_is32;                            // 1 if edge_index is int32
__device__ __align__(16)  int   g_degi  [N_NODES];
__device__ __align__(16)  int   g_off   [N_NODES];
__device__ __align__(16)  int   g_cursor[N_NODES];
__device__ __align__(16)  int   g_part  [SCAN_NB];
__device__ __align__(16)  int   g_part2 [SCAN_NB];
__device__ __align__(16)  int   g_csr   [N_EDGES]; // src ids grouped by dst
__device__ __align__(16)  float g_dinv[N_NODES];
__device__ __align__(128) float g_y1  [N_NODES * F_HID];
__device__ __align__(128) float g_y2  [N_NODES * F_HID];   // layer-2 msgs (W2 deferred)

// ---------------- kernels ----------------

// Zero degree + detect index dtype (thread 0, 64 pipelined loads, no break).
__global__ void k_init(const long long* __restrict__ ei64) {
    int i = blockIdx.x * blockDim.x + threadIdx.x;
    if (i < N_NODES) g_degi[i] = 0;
    if (i == 0) {
        int is32 = 0;
#pragma unroll
        for (int k = 0; k < 64; k++) {
            long long v = ei64[k];
            is32 |= (v < 0) | (v >= (long long)N_NODES);
        }
        g_is32 = is32 ? 1 : 0;
    }
}

// In-degree histogram from dst column only.
__global__ void __launch_bounds__(256) k_degree(const void* __restrict__ ei) {
    int e = blockIdx.x * blockDim.x + threadIdx.x;
    if (e >= N_EDGES) return;
    int d;
    if (g_is32) d = __ldcs(&((const int*)ei)[N_EDGES + e]);
    else        d = (int)__ldcs(&((const long long*)ei)[N_EDGES + e]);
    atomicAdd(&g_degi[d], 1);
}

// ---- 3-kernel exclusive scan over g_degi -> g_off (and cursors) ----
__global__ void __launch_bounds__(SCAN_B) k_scanA() {
    __shared__ int sh[SCAN_B];
    int i = blockIdx.x * SCAN_B + threadIdx.x;
    int v = (i < N_NODES) ? g_degi[i] : 0;
    sh[threadIdx.x] = v;
    __syncthreads();
#pragma unroll
    for (int off = 1; off < SCAN_B; off <<= 1) {
        int t = (threadIdx.x >= off) ? sh[threadIdx.x - off] : 0;
        __syncthreads();
        if (threadIdx.x >= off) sh[threadIdx.x] += t;
        __syncthreads();
    }
    int incl = sh[threadIdx.x];
    if (i < N_NODES) g_off[i] = incl - v;      // block-local exclusive
    if (threadIdx.x == SCAN_B - 1) g_part[blockIdx.x] = incl;
}

__global__ void __launch_bounds__(256) k_scanB() {
    __shared__ int sh[256];
    int v = (threadIdx.x < SCAN_NB) ? g_part[threadIdx.x] : 0;
    sh[threadIdx.x] = v;
    __syncthreads();
#pragma unroll
    for (int off = 1; off < 256; off <<= 1) {
        int t = (threadIdx.x >= off) ? sh[threadIdx.x - off] : 0;
        __syncthreads();
        if (threadIdx.x >= off) sh[threadIdx.x] += t;
        __syncthreads();
    }
    if (threadIdx.x < SCAN_NB) g_part2[threadIdx.x] = sh[threadIdx.x] - v;  // exclusive
}

__global__ void __launch_bounds__(SCAN_B) k_scanC() {
    int i = blockIdx.x * SCAN_B + threadIdx.x;
    if (i < N_NODES) {
        int o = g_off[i] + g_part2[blockIdx.x];
        g_off[i] = o;
        g_cursor[i] = o;
    }
}

// Scatter edges into CSR slots (grouped by dst).
__global__ void __launch_bounds__(256) k_fill(const void* __restrict__ ei) {
    int e = blockIdx.x * blockDim.x + threadIdx.x;
    if (e >= N_EDGES) return;
    int s, d;
    if (g_is32) {
        const int* p = (const int*)ei;
        s = __ldcs(&p[e]);
        d = __ldcs(&p[N_EDGES + e]);
    } else {
        const long long* p = (const long long*)ei;
        s = (int)__ldcs(&p[e]);
        d = (int)__ldcs(&p[N_EDGES + e]);
    }
    int slot = atomicAdd(&g_cursor[d], 1);
    g_csr[slot] = s;
}

// Tiled GEMM1: 256 nodes/block, K chunked by 32 via smem (stride-33: conflict-free).
// y1 = dinv * (x @ W1); also writes dinv.
__global__ void __launch_bounds__(256) k_gemm1(const float* __restrict__ x,
                                               const float* __restrict__ W1) {
    __shared__ float Ws[F_IN * F_HID];   // 8 KB
    __shared__ float xs[256 * 33];       // 33 KB
    for (int i = threadIdx.x; i < F_IN * F_HID; i += blockDim.x) Ws[i] = W1[i];

    int t = threadIdx.x;
    int base = blockIdx.x * 256;

    float acc[F_HID];
#pragma unroll
    for (int j = 0; j < F_HID; j++) acc[j] = 0.0f;

    for (int kc = 0; kc < F_IN; kc += 32) {
        __syncthreads();
#pragma unroll
        for (int it = 0; it < 8; it++) {
            int f  = it * 256 + t;
            int r  = f >> 3;
            int c4 = f & 7;
            int nn = min(base + r, N_NODES - 1);
            float4 v = __ldcs((const float4*)(x + (size_t)nn * F_IN + kc) + c4);
            float* dp = &xs[r * 33 + c4 * 4];
            dp[0] = v.x; dp[1] = v.y; dp[2] = v.z; dp[3] = v.w;
        }
        __syncthreads();
#pragma unroll
        for (int k = 0; k < 32; k++) {
            float xv = xs[t * 33 + k];                               // conflict-free
            const float4* wr = (const float4*)&Ws[(kc + k) * F_HID]; // broadcast
            float4 w0 = wr[0], w1 = wr[1], w2 = wr[2], w3 = wr[3];
            acc[0]  += xv * w0.x;  acc[1]  += xv * w0.y;
            acc[2]  += xv * w0.z;  acc[3]  += xv * w0.w;
            acc[4]  += xv * w1.x;  acc[5]  += xv * w1.y;
            acc[6]  += xv * w1.z;  acc[7]  += xv * w1.w;
            acc[8]  += xv * w2.x;  acc[9]  += xv * w2.y;
            acc[10] += xv * w2.z;  acc[11] += xv * w2.w;
            acc[12] += xv * w3.x;  acc[13] += xv * w3.y;
            acc[14] += xv * w3.z;  acc[15] += xv * w3.w;
        }
    }

    int n = base + t;
    if (n >= N_NODES) return;
    float dinv = rsqrtf((float)(g_degi[n] + 1));   // +1 self-loop
    g_dinv[n] = dinv;
    float4* y = (float4*)&g_y1[(size_t)n * F_HID];
#pragma unroll
    for (int j = 0; j < F_HID / 4; j++) {
        float4 v;
        v.x = acc[4 * j + 0] * dinv;
        v.y = acc[4 * j + 1] * dinv;
        v.z = acc[4 * j + 2] * dinv;
        v.w = acc[4 * j + 3] * dinv;
        y[j] = v;
    }
}

// Layer-1 aggregation + fused layer-2 prep.
// Warp per node, 4 lanes per edge. After xor 4/8/16 every lane holds the full
// aggregate for its c4 group. Then y2 = relu(dinv*(agg+self) + b1)*dinv.
__global__ void __launch_bounds__(256) k_agg1(const float* __restrict__ b1) {
    int n = (blockIdx.x * blockDim.x + threadIdx.x) >> 5;
    if (n >= N_NODES) return;
    int lane = threadIdx.x & 31;
    int sub  = lane >> 2;
    int c4   = lane & 3;

    int beg = g_off[n];
    int deg = g_degi[n];

    float4 a = make_float4(0.f, 0.f, 0.f, 0.f);
    for (int i = sub; i < deg; i += 8) {
        int src = __ldg(&g_csr[beg + i]);
        float4 v = ((const float4*)(g_y1 + (size_t)src * F_HID))[c4];
        a.x += v.x; a.y += v.y; a.z += v.z; a.w += v.w;
    }
#pragma unroll
    for (int off = 4; off <= 16; off <<= 1) {
        a.x += __shfl_xor_sync(0xFFFFFFFFu, a.x, off);
        a.y += __shfl_xor_sync(0xFFFFFFFFu, a.y, off);
        a.z += __shfl_xor_sync(0xFFFFFFFFu, a.z, off);
        a.w += __shfl_xor_sync(0xFFFFFFFFu, a.w, off);
    }
    if (lane < 4) {
        float4 self = ((const float4*)(g_y1 + (size_t)n * F_HID))[c4];
        float dinv = g_dinv[n];
        const float4 bb = ((const float4*)b1)[c4];
        float4 t;
        t.x = fmaxf((a.x + self.x) * dinv + bb.x, 0.0f) * dinv;
        t.y = fmaxf((a.y + self.y) * dinv + bb.y, 0.0f) * dinv;
        t.z = fmaxf((a.z + self.z) * dinv + bb.z, 0.0f) * dinv;
        t.w = fmaxf((a.w + self.w) * dinv + bb.w, 0.0f) * dinv;
        ((float4*)(g_y2 + (size_t)n * F_HID))[c4] = t;
    }
}

// Layer-2 aggregation + fused W2 GEMM + bias + log_softmax, writes output.
__global__ void __launch_bounds__(256) k_agg2(const float* __restrict__ W2,
                                              const float* __restrict__ b2,
                                              float* __restrict__ out) {
    __shared__ float Ws[F_HID * F_OUT];  // 320 floats
    __shared__ float bs[F_OUT];
    for (int i = threadIdx.x; i < F_HID * F_OUT; i += blockDim.x) Ws[i] = W2[i];
    if (threadIdx.x < F_OUT) bs[threadIdx.x] = b2[threadIdx.x];
    __syncthreads();

    int n = (blockIdx.x * blockDim.x + threadIdx.x) >> 5;
    if (n >= N_NODES) return;
    int lane = threadIdx.x & 31;
    int sub  = lane >> 2;
    int c4   = lane & 3;

    int beg = g_off[n];
    int deg = g_degi[n];

    float4 a = make_float4(0.f, 0.f, 0.f, 0.f);
    for (int i = sub; i < deg; i += 8) {
        int src = __ldg(&g_csr[beg + i]);
        float4 v = ((const float4*)(g_y2 + (size_t)src * F_HID))[c4];
        a.x += v.x; a.y += v.y; a.z += v.z; a.w += v.w;
    }
#pragma unroll
    for (int off = 4; off <= 16; off <<= 1) {
        a.x += __shfl_xor_sync(0xFFFFFFFFu, a.x, off);
        a.y += __shfl_xor_sync(0xFFFFFFFFu, a.y, off);
        a.z += __shfl_xor_sync(0xFFFFFFFFu, a.z, off);
        a.w += __shfl_xor_sync(0xFFFFFFFFu, a.w, off);
    }
    // every lane: h[4*c4 .. 4*c4+3] = dinv * (agg + self)
    float dinv = g_dinv[n];
    float4 self = ((const float4*)(g_y2 + (size_t)n * F_HID))[c4];
    float h0 = (a.x + self.x) * dinv;
    float h1 = (a.y + self.y) * dinv;
    float h2 = (a.z + self.z) * dinv;
    float h3 = (a.w + self.w) * dinv;

    // partial logits for this lane's 4 k's; bias added once (c4 == 0 lanes)
    float l[F_OUT];
    int k0 = 4 * c4;
#pragma unroll
    for (int j = 0; j < F_OUT; j++) {
        float acc = (c4 == 0) ? bs[j] : 0.0f;
        acc += h0 * Ws[(k0 + 0) * F_OUT + j];
        acc += h1 * Ws[(k0 + 1) * F_OUT + j];
        acc += h2 * Ws[(k0 + 2) * F_OUT + j];
        acc += h3 * Ws[(k0 + 3) * F_OUT + j];
        l[j] = acc;
    }
    // reduce over the 4 c4 groups (xor 1, 2) -> every lane has all 20 logits
#pragma unroll
    for (int off = 1; off <= 2; off <<= 1) {
#pragma unroll
        for (int j = 0; j < F_OUT; j++)
            l[j] += __shfl_xor_sync(0xFFFFFFFFu, l[j], off);
    }

    float m = l[0];
#pragma unroll
    for (int j = 1; j < F_OUT; j++) m = fmaxf(m, l[j]);
    float s = 0.0f;
#pragma unroll
    for (int j = 0; j < F_OUT; j++) s += expf(l[j] - m);
    float lse = m + logf(s);

    if (lane < 5) {
        float4 t;
        t.x = l[4 * lane + 0] - lse;
        t.y = l[4 * lane + 1] - lse;
        t.z = l[4 * lane + 2] - lse;
        t.w = l[4 * lane + 3] - lse;
        ((float4*)(out + (size_t)n * F_OUT))[lane] = t;
    }
}

// ---------------- launch ----------------
extern "C" void kernel_launch(void* const* d_in, const int* in_sizes, int n_in,
                              void* d_out, int out_size) {
    // Bind inputs BY ELEMENT COUNT:
    //   x:12,800,000  edge_index:6,400,000  W1:2048  b1:16  W2:320  b2:20
    const float* x  = nullptr;
    const void*  ei = nullptr;
    const float* W1 = nullptr;
    const float* b1 = nullptr;
    const float* W2 = nullptr;
    const float* b2 = nullptr;

    for (int i = 0; i < n_in; i++) {
        switch (in_sizes[i]) {
            case 12800000: x  = (const float*)d_in[i]; break;
            case  6400000: ei = d_in[i];               break;
            case     2048: W1 = (const float*)d_in[i]; break;
            case       16: b1 = (const float*)d_in[i]; break;
            case      320: W2 = (const float*)d_in[i]; break;
            case       20: b2 = (const float*)d_in[i]; break;
            default: break;
        }
    }
    if (!x || !ei || !W1 || !b1 || !W2 || !b2) return;

    float* out = (float*)d_out;

    const int nodeBlocks256 = (N_NODES + 255) / 256;
    const int edgeBlocks256 = (N_EDGES + 255) / 256;
    const int aggBlocks     = (N_NODES * 32 + 255) / 256;   // warp per node

    k_init   <<<nodeBlocks256, 256>>>((const long long*)ei);
    k_degree <<<edgeBlocks256, 256>>>(ei);
    k_scanA  <<<SCAN_NB, SCAN_B>>>();
    k_scanB  <<<1, 256>>>();
    k_scanC  <<<SCAN_NB, SCAN_B>>>();
    k_fill   <<<edgeBlocks256, 256>>>(ei);
    k_gemm1  <<<nodeBlocks256, 256>>>(x, W1);
    k_agg1   <<<aggBlocks, 256>>>(b1);
    k_agg2   <<<aggBlocks, 256>>>(W2, b2, out);
}

// round 8
// speedup vs baseline: 1.4143x; 1.4143x over previous
#include <cuda_runtime.h>
#include <cstdint>

#define N_NODES 100000
#define N_EDGES 3200000
#define F_IN    128
#define F_HID   16
#define F_OUT   20

#define SCAN_B  512
#define SCAN_NB ((N_NODES + SCAN_B - 1) / SCAN_B)   // 196

// ---------------- scratch (static device globals; no allocation) ----------------
__device__ int g_is32;                            // 1 if edge_index is int32
__device__ __align__(16)  int   g_degi  [N_NODES];
__device__ __align__(16)  int   g_off   [N_NODES];
__device__ __align__(16)  int   g_cursor[N_NODES];
__device__ __align__(16)  int   g_part  [SCAN_NB];
__device__ __align__(16)  int   g_part2 [SCAN_NB];
__device__ __align__(16)  int   g_csr   [N_EDGES]; // src ids grouped by dst
__device__ __align__(16)  float g_dinv[N_NODES];
__device__ __align__(128) float g_y1  [N_NODES * F_HID];
__device__ __align__(128) float g_y2  [N_NODES * F_HID];   // layer-2 msgs (W2 deferred)

// ---------------- kernels ----------------

// Zero degree + detect index dtype (thread 0, 64 pipelined loads, no break).
__global__ void k_init(const long long* __restrict__ ei64) {
    int i = blockIdx.x * blockDim.x + threadIdx.x;
    if (i < N_NODES) g_degi[i] = 0;
    if (i == 0) {
        int is32 = 0;
#pragma unroll
        for (int k = 0; k < 64; k++) {
            long long v = ei64[k];
            is32 |= (v < 0) | (v >= (long long)N_NODES);
        }
        g_is32 = is32 ? 1 : 0;
    }
}

// In-degree histogram from dst column only.
__global__ void __launch_bounds__(256) k_degree(const void* __restrict__ ei) {
    int e = blockIdx.x * blockDim.x + threadIdx.x;
    if (e >= N_EDGES) return;
    int d;
    if (g_is32) d = __ldcs(&((const int*)ei)[N_EDGES + e]);
    else        d = (int)__ldcs(&((const long long*)ei)[N_EDGES + e]);
    atomicAdd(&g_degi[d], 1);
}

// ---- 3-kernel exclusive scan over g_degi -> g_off (and cursors) ----
__global__ void __launch_bounds__(SCAN_B) k_scanA() {
    __shared__ int sh[SCAN_B];
    int i = blockIdx.x * SCAN_B + threadIdx.x;
    int v = (i < N_NODES) ? g_degi[i] : 0;
    sh[threadIdx.x] = v;
    __syncthreads();
#pragma unroll
    for (int off = 1; off < SCAN_B; off <<= 1) {
        int t = (threadIdx.x >= off) ? sh[threadIdx.x - off] : 0;
        __syncthreads();
        if (threadIdx.x >= off) sh[threadIdx.x] += t;
        __syncthreads();
    }
    int incl = sh[threadIdx.x];
    if (i < N_NODES) g_off[i] = incl - v;      // block-local exclusive
    if (threadIdx.x == SCAN_B - 1) g_part[blockIdx.x] = incl;
}

__global__ void __launch_bounds__(256) k_scanB() {
    __shared__ int sh[256];
    int v = (threadIdx.x < SCAN_NB) ? g_part[threadIdx.x] : 0;
    sh[threadIdx.x] = v;
    __syncthreads();
#pragma unroll
    for (int off = 1; off < 256; off <<= 1) {
        int t = (threadIdx.x >= off) ? sh[threadIdx.x - off] : 0;
        __syncthreads();
        if (threadIdx.x >= off) sh[threadIdx.x] += t;
        __syncthreads();
    }
    if (threadIdx.x < SCAN_NB) g_part2[threadIdx.x] = sh[threadIdx.x] - v;  // exclusive
}

__global__ void __launch_bounds__(SCAN_B) k_scanC() {
    int i = blockIdx.x * SCAN_B + threadIdx.x;
    if (i < N_NODES) {
        int o = g_off[i] + g_part2[blockIdx.x];
        g_off[i] = o;
        g_cursor[i] = o;
    }
}

// Scatter edges into CSR slots (grouped by dst).
__global__ void __launch_bounds__(256) k_fill(const void* __restrict__ ei) {
    int e = blockIdx.x * blockDim.x + threadIdx.x;
    if (e >= N_EDGES) return;
    int s, d;
    if (g_is32) {
        const int* p = (const int*)ei;
        s = __ldcs(&p[e]);
        d = __ldcs(&p[N_EDGES + e]);
    } else {
        const long long* p = (const long long*)ei;
        s = (int)__ldcs(&p[e]);
        d = (int)__ldcs(&p[N_EDGES + e]);
    }
    int slot = atomicAdd(&g_cursor[d], 1);
    g_csr[slot] = s;
}

// Tiled GEMM1: 256 nodes/block, K chunked by 32 via smem (stride-33: conflict-free).
// y1 = dinv * (x @ W1); also writes dinv.
__global__ void __launch_bounds__(256) k_gemm1(const float* __restrict__ x,
                                               const float* __restrict__ W1) {
    __shared__ float Ws[F_IN * F_HID];   // 8 KB
    __shared__ float xs[256 * 33];       // 33 KB
    for (int i = threadIdx.x; i < F_IN * F_HID; i += blockDim.x) Ws[i] = W1[i];

    int t = threadIdx.x;
    int base = blockIdx.x * 256;

    float acc[F_HID];
#pragma unroll
    for (int j = 0; j < F_HID; j++) acc[j] = 0.0f;

    for (int kc = 0; kc < F_IN; kc += 32) {
        __syncthreads();
#pragma unroll
        for (int it = 0; it < 8; it++) {
            int f  = it * 256 + t;
            int r  = f >> 3;
            int c4 = f & 7;
            int nn = min(base + r, N_NODES - 1);
            float4 v = __ldcs((const float4*)(x + (size_t)nn * F_IN + kc) + c4);
            float* dp = &xs[r * 33 + c4 * 4];
            dp[0] = v.x; dp[1] = v.y; dp[2] = v.z; dp[3] = v.w;
        }
        __syncthreads();
#pragma unroll
        for (int k = 0; k < 32; k++) {
            float xv = xs[t * 33 + k];                               // conflict-free
            const float4* wr = (const float4*)&Ws[(kc + k) * F_HID]; // broadcast
            float4 w0 = wr[0], w1 = wr[1], w2 = wr[2], w3 = wr[3];
            acc[0]  += xv * w0.x;  acc[1]  += xv * w0.y;
            acc[2]  += xv * w0.z;  acc[3]  += xv * w0.w;
            acc[4]  += xv * w1.x;  acc[5]  += xv * w1.y;
            acc[6]  += xv * w1.z;  acc[7]  += xv * w1.w;
            acc[8]  += xv * w2.x;  acc[9]  += xv * w2.y;
            acc[10] += xv * w2.z;  acc[11] += xv * w2.w;
            acc[12] += xv * w3.x;  acc[13] += xv * w3.y;
            acc[14] += xv * w3.z;  acc[15] += xv * w3.w;
        }
    }

    int n = base + t;
    if (n >= N_NODES) return;
    float dinv = rsqrtf((float)(g_degi[n] + 1));   // +1 self-loop
    g_dinv[n] = dinv;
    float4* y = (float4*)&g_y1[(size_t)n * F_HID];
#pragma unroll
    for (int j = 0; j < F_HID / 4; j++) {
        float4 v;
        v.x = acc[4 * j + 0] * dinv;
        v.y = acc[4 * j + 1] * dinv;
        v.z = acc[4 * j + 2] * dinv;
        v.w = acc[4 * j + 3] * dinv;
        y[j] = v;
    }
}

// Layer-1 aggregation + fused layer-2 prep.
// Warp per node, 4 lanes per edge. After xor 4/8/16 every lane holds the full
// aggregate for its c4 group. Then y2 = relu(dinv*(agg+self) + b1)*dinv.
__global__ void __launch_bounds__(256) k_agg1(const float* __restrict__ b1) {
    int n = (blockIdx.x * blockDim.x + threadIdx.x) >> 5;
    if (n >= N_NODES) return;
    int lane = threadIdx.x & 31;
    int sub  = lane >> 2;
    int c4   = lane & 3;

    int beg = g_off[n];
    int deg = g_degi[n];

    float4 a = make_float4(0.f, 0.f, 0.f, 0.f);
    for (int i = sub; i < deg; i += 8) {
        int src = __ldg(&g_csr[beg + i]);
        float4 v = ((const float4*)(g_y1 + (size_t)src * F_HID))[c4];
        a.x += v.x; a.y += v.y; a.z += v.z; a.w += v.w;
    }
#pragma unroll
    for (int off = 4; off <= 16; off <<= 1) {
        a.x += __shfl_xor_sync(0xFFFFFFFFu, a.x, off);
        a.y += __shfl_xor_sync(0xFFFFFFFFu, a.y, off);
        a.z += __shfl_xor_sync(0xFFFFFFFFu, a.z, off);
        a.w += __shfl_xor_sync(0xFFFFFFFFu, a.w, off);
    }
    if (lane < 4) {
        float4 self = ((const float4*)(g_y1 + (size_t)n * F_HID))[c4];
        float dinv = g_dinv[n];
        const float4 bb = ((const float4*)b1)[c4];
        float4 t;
        t.x = fmaxf((a.x + self.x) * dinv + bb.x, 0.0f) * dinv;
        t.y = fmaxf((a.y + self.y) * dinv + bb.y, 0.0f) * dinv;
        t.z = fmaxf((a.z + self.z) * dinv + bb.z, 0.0f) * dinv;
        t.w = fmaxf((a.w + self.w) * dinv + bb.w, 0.0f) * dinv;
        ((float4*)(g_y2 + (size_t)n * F_HID))[c4] = t;
    }
}

// Layer-2 aggregation + fused W2 GEMM + bias + log_softmax (lane-parallel).
// After the xor reduce, lane g (g<4) holds h-group g. 16 shuffles broadcast all
// 16 h to every lane; lane j (<20) computes ONLY logit j; softmax via shuffle
// reductions with 1 expf per lane; lanes 0..19 store scalars (80B contiguous).
__global__ void __launch_bounds__(256) k_agg2(const float* __restrict__ W2,
                                              const float* __restrict__ b2,
                                              float* __restrict__ out) {
    __shared__ float Ws[F_HID * F_OUT];  // 320 floats
    __shared__ float bs[F_OUT];
    for (int i = threadIdx.x; i < F_HID * F_OUT; i += blockDim.x) Ws[i] = W2[i];
    if (threadIdx.x < F_OUT) bs[threadIdx.x] = b2[threadIdx.x];
    __syncthreads();

    int n = (blockIdx.x * blockDim.x + threadIdx.x) >> 5;
    if (n >= N_NODES) return;
    int lane = threadIdx.x & 31;
    int sub  = lane >> 2;
    int c4   = lane & 3;

    int beg = g_off[n];
    int deg = g_degi[n];

    float4 a = make_float4(0.f, 0.f, 0.f, 0.f);
    for (int i = sub; i < deg; i += 8) {
        int src = __ldg(&g_csr[beg + i]);
        float4 v = ((const float4*)(g_y2 + (size_t)src * F_HID))[c4];
        a.x += v.x; a.y += v.y; a.z += v.z; a.w += v.w;
    }
#pragma unroll
    for (int off = 4; off <= 16; off <<= 1) {
        a.x += __shfl_xor_sync(0xFFFFFFFFu, a.x, off);
        a.y += __shfl_xor_sync(0xFFFFFFFFu, a.y, off);
        a.z += __shfl_xor_sync(0xFFFFFFFFu, a.z, off);
        a.w += __shfl_xor_sync(0xFFFFFFFFu, a.w, off);
    }

    // this lane's h-group (c4): h[4*c4 + 0..3]
    float dinv = g_dinv[n];
    float4 self = ((const float4*)(g_y2 + (size_t)n * F_HID))[c4];
    float h0 = (a.x + self.x) * dinv;
    float h1 = (a.y + self.y) * dinv;
    float h2 = (a.z + self.z) * dinv;
    float h3 = (a.w + self.w) * dinv;

    // broadcast all 16 h to every lane (lane g<4 owns group g)
    float hh[F_HID];
#pragma unroll
    for (int g = 0; g < 4; g++) {
        hh[4 * g + 0] = __shfl_sync(0xFFFFFFFFu, h0, g);
        hh[4 * g + 1] = __shfl_sync(0xFFFFFFFFu, h1, g);
        hh[4 * g + 2] = __shfl_sync(0xFFFFFFFFu, h2, g);
        hh[4 * g + 3] = __shfl_sync(0xFFFFFFFFu, h3, g);
    }

    // lane j computes logit j only (consecutive lanes -> consecutive banks)
    const float NEG_INF = __int_as_float(0xff800000);
    float lj = NEG_INF;
    if (lane < F_OUT) {
        lj = bs[lane];
#pragma unroll
        for (int k = 0; k < F_HID; k++) lj += hh[k] * Ws[k * F_OUT + lane];
    }

    // warp softmax: max reduce, 1 expf/lane, sum reduce
    float m = lj;
#pragma unroll
    for (int off = 16; off >= 1; off >>= 1)
        m = fmaxf(m, __shfl_xor_sync(0xFFFFFFFFu, m, off));
    float e = (lane < F_OUT) ? expf(lj - m) : 0.0f;
    float s = e;
#pragma unroll
    for (int off = 16; off >= 1; off >>= 1)
        s += __shfl_xor_sync(0xFFFFFFFFu, s, off);
    float lse = m + logf(s);

    if (lane < F_OUT) out[(size_t)n * F_OUT + lane] = lj - lse;
}

// ---------------- launch ----------------
extern "C" void kernel_launch(void* const* d_in, const int* in_sizes, int n_in,
                              void* d_out, int out_size) {
    // Bind inputs BY ELEMENT COUNT:
    //   x:12,800,000  edge_index:6,400,000  W1:2048  b1:16  W2:320  b2:20
    const float* x  = nullptr;
    const void*  ei = nullptr;
    const float* W1 = nullptr;
    const float* b1 = nullptr;
    const float* W2 = nullptr;
    const float* b2 = nullptr;

    for (int i = 0; i < n_in; i++) {
        switch (in_sizes[i]) {
            case 12800000: x  = (const float*)d_in[i]; break;
            case  6400000: ei = d_in[i];               break;
            case     2048: W1 = (const float*)d_in[i]; break;
            case       16: b1 = (const float*)d_in[i]; break;
            case      320: W2 = (const float*)d_in[i]; break;
            case       20: b2 = (const float*)d_in[i]; break;
            default: break;
        }
    }
    if (!x || !ei || !W1 || !b1 || !W2 || !b2) return;

    float* out = (float*)d_out;

    const int nodeBlocks256 = (N_NODES + 255) / 256;
    const int edgeBlocks256 = (N_EDGES + 255) / 256;
    const int aggBlocks     = (N_NODES * 32 + 255) / 256;   // warp per node

    k_init   <<<nodeBlocks256, 256>>>((const long long*)ei);
    k_degree <<<edgeBlocks256, 256>>>(ei);
    k_scanA  <<<SCAN_NB, SCAN_B>>>();
    k_scanB  <<<1, 256>>>();
    k_scanC  <<<SCAN_NB, SCAN_B>>>();
    k_fill   <<<edgeBlocks256, 256>>>(ei);
    k_gemm1  <<<nodeBlocks256, 256>>>(x, W1);
    k_agg1   <<<aggBlocks, 256>>>(b1);
    k_agg2   <<<aggBlocks, 256>>>(W2, b2, out);
}